// round 16
// baseline (speedup 1.0000x reference)
#include <cuda_runtime.h>
#include <cuda_bf16.h>
#include <cstdint>

#define BATCH 8192
#define NV    1000
#define CHEBK 5
#define NF    5
#define HIDD  256
#define NOUT  10
#define KPAD  640
#define MAXW  32
#define BT    8
#define HBT   4
#define NSLOT 1024
#define PLANE (NV * HBT)

// ---------------- scratch ----------------
__device__ int2  g_ell[NV * MAXW];
__device__ int   g_ell_len[NV];
__device__ int   g_perm[NV];
__device__ int2  g_ellT[(NSLOT / 32) * MAXW * 32];
__device__ __nv_bfloat16 g_poolh[(size_t)BATCH * KPAD];   // pads (625..639) stay 0
__device__ __nv_bfloat16 g_pooll[(size_t)BATCH * KPAD];
__device__ __nv_bfloat16 g_fc1h[HIDD * KPAD];
__device__ __nv_bfloat16 g_fc1l[HIDD * KPAD];
__device__ __nv_bfloat16 g_lin1h[HIDD * HIDD];
__device__ __nv_bfloat16 g_lin1l[HIDD * HIDD];
__device__ __nv_bfloat16 g_z1h[(size_t)BATCH * HIDD];
__device__ __nv_bfloat16 g_z1l[(size_t)BATCH * HIDD];
__device__ float g_z2[(size_t)BATCH * HIDD];

// ---------------- helpers ----------------
__device__ __forceinline__ uint32_t smem_u32(const void* p) {
    uint32_t a;
    asm("{ .reg .u64 t; cvta.to.shared.u64 t, %1; cvt.u32.u64 %0, t; }" : "=r"(a) : "l"(p));
    return a;
}
__device__ __forceinline__ void bf16_split(float x, __nv_bfloat16& h, __nv_bfloat16& l) {
    h = __float2bfloat16(x);
    l = __float2bfloat16(x - __bfloat162float(h));
}
__device__ __forceinline__ void ldm_x4(uint32_t addr, uint32_t* r) {
    asm volatile("ldmatrix.sync.aligned.m8n8.x4.shared.b16 {%0,%1,%2,%3}, [%4];"
                 : "=r"(r[0]), "=r"(r[1]), "=r"(r[2]), "=r"(r[3]) : "r"(addr));
}
__device__ __forceinline__ void mma_bf16(float* d, const uint32_t* a, const uint32_t* b) {
    asm volatile("mma.sync.aligned.m16n8k16.row.col.f32.bf16.bf16.f32 "
                 "{%0,%1,%2,%3}, {%4,%5,%6,%7}, {%8,%9}, {%0,%1,%2,%3};"
                 : "+f"(d[0]), "+f"(d[1]), "+f"(d[2]), "+f"(d[3])
                 : "r"(a[0]), "r"(a[1]), "r"(a[2]), "r"(a[3]), "r"(b[0]), "r"(b[1]));
}
#define CP16(dst, src) \
    asm volatile("cp.async.ca.shared.global [%0], [%1], 16;" :: "r"(dst), "l"(src))
#define CP_COMMIT() asm volatile("cp.async.commit_group;")
#define CP_WAIT1()  asm volatile("cp.async.wait_group 1;")
#define CP_WAIT0()  asm volatile("cp.async.wait_group 0;")

// ---------------- kernel 1: build ELL of Lr = 2*L/lmax - I (warp/row) ----------------
__global__ void build_ell(const float* __restrict__ L, const float* __restrict__ lmax) {
    const int warp = (blockIdx.x * blockDim.x + threadIdx.x) >> 5;
    const int lane = threadIdx.x & 31;
    if (warp >= NV) return;
    const int v = warp;
    const float inv = 2.0f / lmax[0];
    int cnt = 0;
    #pragma unroll 4
    for (int c = 0; c < (NV + 31) / 32; ++c) {
        const int u = c * 32 + lane;
        float val = 0.0f;
        if (u < NV) val = L[(size_t)v * NV + u] * inv - (u == v ? 1.0f : 0.0f);
        const bool nz = (val != 0.0f);
        const unsigned m = __ballot_sync(0xffffffffu, nz);
        if (nz) {
            const int idx = cnt + __popc(m & ((1u << lane) - 1u));
            if (idx < MAXW) g_ell[v * MAXW + idx] = make_int2(u, __float_as_int(val));
        }
        cnt += __popc(m);
    }
    if (lane == 0) g_ell_len[v] = cnt < MAXW ? cnt : MAXW;
}

// ---------------- kernel 1b: deterministic rank sort (smem staged) ----------------
__global__ void sort_nodes() {
    __shared__ int sl[NV];
    const int tid = threadIdx.x;
    if (tid < NV) sl[tid] = g_ell_len[tid];
    __syncthreads();
    if (tid < NV) {
        const int len = sl[tid];
        int pos = 0;
        for (int u = 0; u < NV; ++u) {
            const int lu = sl[u];
            pos += (lu < len) || (lu == len && u < tid);
        }
        g_perm[pos] = tid;
    }
}

// ---------------- kernel 1c: per-warp balanced gather schedule ----------------
// Conflict cost of a warp's LDS.128 step = max occupancy over the 8 start-position
// classes (v & 7). Greedy: at each step, each lane (in order) places its unused edge
// whose class is least-loaded. Schedule length = max lane degree (no inflation).
// Exhausted lanes emit weight-0 pads on the least-loaded class. Deterministic.
__global__ void schedule_ell() {
    __shared__ int           vsS[32][32];
    __shared__ unsigned char lnS[32][32];
    const int w = threadIdx.x;            // one thread per 32-lane warp-group
    if (w >= 32) return;

    // stage node ids / lens; pack per-lane class nibbles on the fly below
    int maxlen = 0;
    for (int l = 0; l < 32; ++l) {
        const int slot = w * 32 + l;
        int v = 0, len = 0;
        if (slot < NV) { v = g_perm[slot]; len = g_ell_len[v]; }
        vsS[w][l] = v;
        lnS[w][l] = (unsigned char)len;
        if (len > maxlen) maxlen = len;
    }

    unsigned used[32];
    unsigned long long p0S[32], p1S[32];
    for (int l = 0; l < 32; ++l) {
        used[l] = 0u;
        const int v = vsS[w][l], len = lnS[w][l];
        unsigned long long p0 = 0ull, p1 = 0ull;
        for (int j = 0; j < len; ++j) {
            const unsigned long long c = (unsigned long long)(g_ell[v * MAXW + j].x & 7);
            if (j < 16) p0 |= c << (4 * j);
            else        p1 |= c << (4 * (j - 16));
        }
        p0S[l] = p0; p1S[l] = p1;
    }

    for (int s = 0; s < maxlen; ++s) {
        unsigned long long cntp = 0ull;        // 8 classes x 8-bit counters
        for (int l = 0; l < 32; ++l) {
            const int len = lnS[w][l];
            const unsigned u = used[l];
            int2 out;
            if (__popc(u) < len) {
                // current minimum class load (early-exit target)
                int mn = 255;
                #pragma unroll
                for (int c = 0; c < 8; ++c) {
                    const int cc = (int)((cntp >> (8 * c)) & 255ull);
                    if (cc < mn) mn = cc;
                }
                int bestj = -1, bestc = 0, bestn = 1 << 30;
                const unsigned long long p0 = p0S[l], p1 = p1S[l];
                for (int j = 0; j < len; ++j) {
                    if (u & (1u << j)) continue;
                    const int c = (int)(((j < 16) ? (p0 >> (4 * j)) : (p1 >> (4 * (j - 16)))) & 7ull);
                    const int n = (int)((cntp >> (8 * c)) & 255ull);
                    if (n < bestn) { bestn = n; bestj = j; bestc = c; }
                    if (bestn == mn) break;
                }
                used[l] = u | (1u << bestj);
                cntp += 1ull << (8 * bestc);
                out = g_ell[vsS[w][l] * MAXW + bestj];
            } else {
                int bc = 0, bn = 255;
                #pragma unroll
                for (int c = 0; c < 8; ++c) {
                    const int cc = (int)((cntp >> (8 * c)) & 255ull);
                    if (cc < bn) { bn = cc; bc = c; }
                }
                cntp += 1ull << (8 * bc);
                out = make_int2(bc, 0);    // weight-0 pad on balanced class
            }
            g_ellT[w * (MAXW * 32) + s * 32 + l] = out;
        }
    }
}

// ---------------- kernel 1d: weight conversion to bf16 hi/lo ----------------
__global__ void conv_weights(const float* __restrict__ fc1W, const float* __restrict__ lin1W) {
    const int i = blockIdx.x * blockDim.x + threadIdx.x;
    if (i < HIDD * 625) {
        const int n = i / 625, k = i - n * 625;
        __nv_bfloat16 h, l;
        bf16_split(fc1W[i], h, l);
        g_fc1h[n * KPAD + k] = h;
        g_fc1l[n * KPAD + k] = l;
    }
    if (i < HIDD * HIDD) {
        __nv_bfloat16 h, l;
        bf16_split(lin1W[i], h, l);
        g_lin1h[i] = h;
        g_lin1l[i] = l;
    }
}

// ---------------- kernel 2: fused cheby + cl1 + relu + maxpool -> bf16 hi/lo ----------
__global__ __launch_bounds__(1024, 1)
void cheby_fused(const float* __restrict__ x,
                 const float* __restrict__ W,
                 const float* __restrict__ bias) {
    extern __shared__ float sT[];
    float* sLo = sT;
    float* sHi = sT + CHEBK * PLANE;
    float* sW  = sT + 2 * CHEBK * PLANE;
    const int b0  = blockIdx.x * BT;
    const int tid = threadIdx.x;

    if (tid < NF * CHEBK) sW[tid] = W[tid];
    if (tid < NF) sW[NF * CHEBK + tid] = bias[tid];

    #pragma unroll
    for (int i = tid; i < NV * BT; i += 1024) {
        const int bb = i / NV, v = i - bb * NV;
        const float val = x[(size_t)(b0 + bb) * NV + v];
        if (bb < HBT) sLo[v * HBT + bb] = val;
        else          sHi[v * HBT + (bb - HBT)] = val;
    }
    __syncthreads();

    const int slot = tid;
    const int grp  = tid >> 5, lane = tid & 31;
    int v = 0, len = 0;
    if (slot < NV) { v = g_perm[slot]; len = g_ell_len[v]; }
    const int lm = __reduce_max_sync(0xffffffffu, len);
    const int2* __restrict__ ep = g_ellT + grp * (MAXW * 32) + lane;

    #pragma unroll
    for (int k = 1; k < CHEBK; ++k) {
        const float* __restrict__ Lo1 = sLo + (k - 1) * PLANE;
        const float* __restrict__ Hi1 = sHi + (k - 1) * PLANE;
        float4 A0 = make_float4(0.f, 0.f, 0.f, 0.f);
        float4 A1 = make_float4(0.f, 0.f, 0.f, 0.f);
        #pragma unroll 2
        for (int j = 0; j < lm; ++j) {
            const int2 e = __ldg(&ep[j * 32]);
            const float w = __int_as_float(e.y);
            const float4 t0 = *reinterpret_cast<const float4*>(Lo1 + e.x * HBT);
            const float4 t1 = *reinterpret_cast<const float4*>(Hi1 + e.x * HBT);
            A0.x = fmaf(w, t0.x, A0.x); A0.y = fmaf(w, t0.y, A0.y);
            A0.z = fmaf(w, t0.z, A0.z); A0.w = fmaf(w, t0.w, A0.w);
            A1.x = fmaf(w, t1.x, A1.x); A1.y = fmaf(w, t1.y, A1.y);
            A1.z = fmaf(w, t1.z, A1.z); A1.w = fmaf(w, t1.w, A1.w);
        }
        if (slot < NV) {
            float4* toL = reinterpret_cast<float4*>(sLo + k * PLANE + v * HBT);
            float4* toH = reinterpret_cast<float4*>(sHi + k * PLANE + v * HBT);
            if (k == 1) {
                *toL = A0; *toH = A1;
            } else {
                const float4 ma = *reinterpret_cast<const float4*>(sLo + (k - 2) * PLANE + v * HBT);
                const float4 mb = *reinterpret_cast<const float4*>(sHi + (k - 2) * PLANE + v * HBT);
                *toL = make_float4(2.f * A0.x - ma.x, 2.f * A0.y - ma.y,
                                   2.f * A0.z - ma.z, 2.f * A0.w - ma.w);
                *toH = make_float4(2.f * A1.x - mb.x, 2.f * A1.y - mb.y,
                                   2.f * A1.z - mb.z, 2.f * A1.w - mb.w);
            }
        }
        __syncthreads();
    }

    if (tid < 125 * BT) {
        const int bb = tid & (BT - 1);
        const int g  = tid / BT;
        const float* base = (bb < HBT) ? sLo : sHi;
        const int bo = bb & (HBT - 1);
        float m[NF];
        #pragma unroll
        for (int f = 0; f < NF; ++f) m[f] = -3.4e38f;
        #pragma unroll
        for (int vi = 0; vi < 8; ++vi) {
            const int vv = g * 8 + vi;
            float t[CHEBK];
            #pragma unroll
            for (int k = 0; k < CHEBK; ++k) t[k] = base[k * PLANE + vv * HBT + bo];
            #pragma unroll
            for (int f = 0; f < NF; ++f) {
                float s = sW[NF * CHEBK + f];
                #pragma unroll
                for (int k = 0; k < CHEBK; ++k) s = fmaf(sW[f * CHEBK + k], t[k], s);
                m[f] = fmaxf(m[f], s);
            }
        }
        const size_t op = (size_t)(b0 + bb) * KPAD + g * NF;
        #pragma unroll
        for (int f = 0; f < NF; ++f) {
            __nv_bfloat16 h, l;
            bf16_split(fmaxf(m[f], 0.0f), h, l);
            g_poolh[op + f] = h;
            g_pooll[op + f] = l;
        }
    }
}

// ---------------- kernels 3/4: cp.async double-buffered mma.sync bf16-split GEMM ------
#define STG   30720
#define O_AL  10240
#define O_BH  20480
#define O_BL  25600
#define O_EP  61440
#define GSM_TOT (O_EP + 576 * 4)

template <int EPI>
__global__ __launch_bounds__(256, 2)
void gemm_mma(const __nv_bfloat16* __restrict__ Ah, const __nv_bfloat16* __restrict__ Al,
              int lda,
              const __nv_bfloat16* __restrict__ Bh, const __nv_bfloat16* __restrict__ Bl,
              int ldb, int ktiles,
              const float* __restrict__ bias,
              const float* __restrict__ bn_gamma, const float* __restrict__ bn_beta,
              const float* __restrict__ bn_mean,  const float* __restrict__ bn_var,
              float* __restrict__ Cf,
              __nv_bfloat16* __restrict__ Ch, __nv_bfloat16* __restrict__ Cl, int ldc) {
    extern __shared__ char sm[];
    const uint32_t sbase = smem_u32(sm);

    const int tid = threadIdx.x, wid = tid >> 5, lane = tid & 31;
    const int wm = wid >> 1, wn = wid & 1;
    const int m0 = blockIdx.y * 128, n0 = blockIdx.x * 64;

    float acc[2][4][4];
    #pragma unroll
    for (int a = 0; a < 2; ++a)
        #pragma unroll
        for (int b = 0; b < 4; ++b)
            #pragma unroll
            for (int c = 0; c < 4; ++c) acc[a][b][c] = 0.0f;

    const int aRowL = tid >> 2, aOffL = (tid & 3) * 16;
    auto load_tile = [&](int t, int stage) {
        const uint32_t sb = sbase + stage * STG;
        #pragma unroll
        for (int i = 0; i < 2; ++i) {
            const int row = aRowL + i * 64;
            const uint32_t dst = sb + row * 80 + aOffL;
            const size_t go = (size_t)(m0 + row) * lda + t * 32 + (aOffL >> 1);
            CP16(dst, Ah + go);
            CP16(dst + O_AL, Al + go);
        }
        {
            const int row = tid >> 2;
            const uint32_t dst = sb + O_BH + row * 80 + aOffL;
            const size_t go = (size_t)(n0 + row) * ldb + t * 32 + (aOffL >> 1);
            CP16(dst, Bh + go);
            CP16(dst + (O_BL - O_BH), Bl + go);
        }
        CP_COMMIT();
    };

    const int aRow = wm * 32 + (lane & 15);
    const int aCol = (lane >> 4) * 8;
    const int bRow = wn * 32 + ((lane >> 4) * 8) + (lane & 7);
    const int bCol = ((lane >> 3) & 1) * 8;

    load_tile(0, 0);
    int stage = 0;
    for (int t = 0; t < ktiles; ++t) {
        if (t + 1 < ktiles) {
            load_tile(t + 1, stage ^ 1);
            CP_WAIT1();
        } else {
            CP_WAIT0();
        }
        __syncthreads();

        const uint32_t sb = sbase + stage * STG;
        #pragma unroll
        for (int kk = 0; kk < 2; ++kk) {
            uint32_t ah[2][4], al[2][4], bh[2][4], bl[2][4];
            #pragma unroll
            for (int mt = 0; mt < 2; ++mt) {
                const uint32_t off = (uint32_t)((aRow + mt * 16) * 80 + (kk * 16 + aCol) * 2);
                ldm_x4(sb + off, ah[mt]);
                ldm_x4(sb + O_AL + off, al[mt]);
            }
            #pragma unroll
            for (int nt2 = 0; nt2 < 2; ++nt2) {
                const uint32_t off = (uint32_t)((bRow + nt2 * 16) * 80 + (kk * 16 + bCol) * 2);
                ldm_x4(sb + O_BH + off, bh[nt2]);
                ldm_x4(sb + O_BL + off, bl[nt2]);
            }
            #pragma unroll
            for (int mt = 0; mt < 2; ++mt)
                #pragma unroll
                for (int nt = 0; nt < 4; ++nt) {
                    const uint32_t* fh = &bh[nt >> 1][(nt & 1) * 2];
                    const uint32_t* fl = &bl[nt >> 1][(nt & 1) * 2];
                    mma_bf16(acc[mt][nt], ah[mt], fh);
                    mma_bf16(acc[mt][nt], al[mt], fh);
                    mma_bf16(acc[mt][nt], ah[mt], fl);
                }
        }
        __syncthreads();
        stage ^= 1;
    }

    float* sEp = reinterpret_cast<float*>(sm + O_EP);
    if (tid < 64) {
        const int col = n0 + tid;
        sEp[tid] = __ldg(bias + col);
        if (EPI == 0) {
            #pragma unroll
            for (int l = 0; l < 4; ++l) {
                const int idx = l * HIDD + col;
                const float s = __ldg(bn_gamma + idx) * rsqrtf(__ldg(bn_var + idx) + 1e-5f);
                sEp[64 + l * 64 + tid]  = s;
                sEp[320 + l * 64 + tid] = __ldg(bn_beta + idx) - __ldg(bn_mean + idx) * s;
            }
        }
    }
    __syncthreads();

    #pragma unroll
    for (int mt = 0; mt < 2; ++mt) {
        const int row0 = m0 + wm * 32 + mt * 16 + (lane >> 2);
        #pragma unroll
        for (int nt = 0; nt < 4; ++nt) {
            const int cl = wn * 32 + nt * 8 + (lane & 3) * 2;
            const int col = n0 + cl;
            const float* d = acc[mt][nt];
            #pragma unroll
            for (int rr = 0; rr < 2; ++rr) {
                const int row = row0 + rr * 8;
                if (EPI == 0) {
                    __nv_bfloat16 hh[2], ll[2];
                    #pragma unroll
                    for (int q = 0; q < 2; ++q) {
                        float y = d[rr * 2 + q] + sEp[cl + q];
                        float z = 0.0f;
                        #pragma unroll
                        for (int l = 0; l < 4; ++l) {
                            y = fmaxf(fmaf(y, sEp[64 + l * 64 + cl + q],
                                           sEp[320 + l * 64 + cl + q]), 0.0f);
                            z = fmaxf(z, y);
                        }
                        bf16_split(z, hh[q], ll[q]);
                    }
                    __nv_bfloat162 th; th.x = hh[0]; th.y = hh[1];
                    __nv_bfloat162 tl; tl.x = ll[0]; tl.y = ll[1];
                    *reinterpret_cast<__nv_bfloat162*>(&Ch[(size_t)row * ldc + col]) = th;
                    *reinterpret_cast<__nv_bfloat162*>(&Cl[(size_t)row * ldc + col]) = tl;
                } else {
                    float2 o;
                    o.x = fmaxf(d[rr * 2 + 0] + sEp[cl + 0], 0.0f);
                    o.y = fmaxf(d[rr * 2 + 1] + sEp[cl + 1], 0.0f);
                    *reinterpret_cast<float2*>(&Cf[(size_t)row * ldc + col]) = o;
                }
            }
        }
    }
}

// ---------------- kernel 5: lin2 + log_softmax ----------------
__global__ void lin2_lsm(const float* __restrict__ Z2, const float* __restrict__ W2,
                         const float* __restrict__ b2, float* __restrict__ out) {
    const int gw   = (blockIdx.x * blockDim.x + threadIdx.x) >> 5;
    const int lane = threadIdx.x & 31;
    if (gw >= BATCH) return;
    const float* zr = Z2 + (size_t)gw * HIDD;
    float z[8];
    #pragma unroll
    for (int j = 0; j < 8; ++j) z[j] = zr[lane + 32 * j];

    float logit[NOUT];
    #pragma unroll
    for (int o = 0; o < NOUT; ++o) {
        float p = 0.0f;
        #pragma unroll
        for (int j = 0; j < 8; ++j) p += z[j] * __ldg(W2 + o * HIDD + lane + 32 * j);
        #pragma unroll
        for (int off = 16; off; off >>= 1) p += __shfl_xor_sync(0xffffffffu, p, off);
        logit[o] = p + __ldg(b2 + o);
    }
    float m = logit[0];
    #pragma unroll
    for (int o = 1; o < NOUT; ++o) m = fmaxf(m, logit[o]);
    float s = 0.0f;
    #pragma unroll
    for (int o = 0; o < NOUT; ++o) s += expf(logit[o] - m);
    const float lse = m + logf(s);
    if (lane < NOUT) out[(size_t)gw * NOUT + lane] = logit[lane] - lse;
}

// ---------------- launcher ----------------
extern "C" void kernel_launch(void* const* d_in, const int* in_sizes, int n_in,
                              void* d_out, int out_size) {
    const float* x        = (const float*)d_in[0];
    const float* L        = (const float*)d_in[1];
    const float* lmax     = (const float*)d_in[2];
    const float* cl1W     = (const float*)d_in[3];
    const float* cl1b     = (const float*)d_in[4];
    const float* fc1W     = (const float*)d_in[5];
    const float* fc1b     = (const float*)d_in[6];
    const float* bn_gamma = (const float*)d_in[7];
    const float* bn_beta  = (const float*)d_in[8];
    const float* bn_mean  = (const float*)d_in[9];
    const float* bn_var   = (const float*)d_in[10];
    const float* lin1W    = (const float*)d_in[11];
    const float* lin1b    = (const float*)d_in[12];
    const float* lin2W    = (const float*)d_in[13];
    const float* lin2b    = (const float*)d_in[14];
    float* out = (float*)d_out;

    __nv_bfloat16 *pPh, *pPl, *pF1h, *pF1l, *pL1h, *pL1l, *pZ1h, *pZ1l;
    float* pZ2;
    cudaGetSymbolAddress((void**)&pPh,  g_poolh);
    cudaGetSymbolAddress((void**)&pPl,  g_pooll);
    cudaGetSymbolAddress((void**)&pF1h, g_fc1h);
    cudaGetSymbolAddress((void**)&pF1l, g_fc1l);
    cudaGetSymbolAddress((void**)&pL1h, g_lin1h);
    cudaGetSymbolAddress((void**)&pL1l, g_lin1l);
    cudaGetSymbolAddress((void**)&pZ1h, g_z1h);
    cudaGetSymbolAddress((void**)&pZ1l, g_z1l);
    cudaGetSymbolAddress((void**)&pZ2,  g_z2);

    // 1) prep: ELL + sort + balanced gather schedule + weight conversion
    build_ell<<<(NV * 32 + 255) / 256, 256>>>(L, lmax);
    sort_nodes<<<1, 1024>>>();
    schedule_ell<<<1, 32>>>();
    conv_weights<<<(HIDD * 625 + 255) / 256, 256>>>(fc1W, lin1W);

    // 2) fused chebyshev + cl1 + relu + maxpool -> bf16 hi/lo pool
    const int smem = (2 * CHEBK * PLANE + 32) * (int)sizeof(float);  // 160128 B
    cudaFuncSetAttribute(cheby_fused, cudaFuncAttributeMaxDynamicSharedMemorySize, smem);
    cheby_fused<<<BATCH / BT, 1024, smem>>>(x, cl1W, cl1b);

    // 3) fc1 + BN x4 + relu + JK-max  (K=640 padded), double-buffered mma.sync
    cudaFuncSetAttribute(gemm_mma<0>, cudaFuncAttributeMaxDynamicSharedMemorySize, GSM_TOT);
    cudaFuncSetAttribute(gemm_mma<1>, cudaFuncAttributeMaxDynamicSharedMemorySize, GSM_TOT);
    dim3 grid(HIDD / 64, BATCH / 128);   // (4, 64) = 256 CTAs
    gemm_mma<0><<<grid, 256, GSM_TOT>>>(pPh, pPl, KPAD, pF1h, pF1l, KPAD, KPAD / 32,
                                        fc1b, bn_gamma, bn_beta, bn_mean, bn_var,
                                        nullptr, pZ1h, pZ1l, HIDD);

    // 4) lin1 + relu  (K=256)
    gemm_mma<1><<<grid, 256, GSM_TOT>>>(pZ1h, pZ1l, HIDD, pL1h, pL1l, HIDD, HIDD / 32,
                                        lin1b, nullptr, nullptr, nullptr, nullptr,
                                        pZ2, nullptr, nullptr, HIDD);

    // 5) lin2 + log_softmax
    lin2_lsm<<<BATCH / 8, 256>>>(pZ2, lin2W, lin2b, out);
}

// round 17
// speedup vs baseline: 3.7309x; 3.7309x over previous
#include <cuda_runtime.h>
#include <cuda_bf16.h>
#include <cstdint>

#define BATCH 8192
#define NV    1000
#define CHEBK 5
#define NF    5
#define HIDD  256
#define NOUT  10
#define KPAD  640
#define MAXW  32
#define BT    8
#define HBT   4
#define NSLOT 1024
#define PLANE (NV * HBT)

// ---------------- scratch ----------------
__device__ int2  g_ell[NV * MAXW];
__device__ int   g_ell_len[NV];
__device__ int   g_perm[NV];
__device__ int2  g_ellT[(NSLOT / 32) * MAXW * 32];
__device__ __nv_bfloat16 g_poolh[(size_t)BATCH * KPAD];   // pads (625..639) stay 0
__device__ __nv_bfloat16 g_pooll[(size_t)BATCH * KPAD];
__device__ __nv_bfloat16 g_fc1h[HIDD * KPAD];
__device__ __nv_bfloat16 g_fc1l[HIDD * KPAD];
__device__ __nv_bfloat16 g_lin1h[HIDD * HIDD];
__device__ __nv_bfloat16 g_lin1l[HIDD * HIDD];
__device__ __nv_bfloat16 g_z1h[(size_t)BATCH * HIDD];
__device__ __nv_bfloat16 g_z1l[(size_t)BATCH * HIDD];
__device__ float g_z2[(size_t)BATCH * HIDD];

// ---------------- helpers ----------------
__device__ __forceinline__ uint32_t smem_u32(const void* p) {
    uint32_t a;
    asm("{ .reg .u64 t; cvta.to.shared.u64 t, %1; cvt.u32.u64 %0, t; }" : "=r"(a) : "l"(p));
    return a;
}
__device__ __forceinline__ void bf16_split(float x, __nv_bfloat16& h, __nv_bfloat16& l) {
    h = __float2bfloat16(x);
    l = __float2bfloat16(x - __bfloat162float(h));
}
__device__ __forceinline__ void ldm_x4(uint32_t addr, uint32_t* r) {
    asm volatile("ldmatrix.sync.aligned.m8n8.x4.shared.b16 {%0,%1,%2,%3}, [%4];"
                 : "=r"(r[0]), "=r"(r[1]), "=r"(r[2]), "=r"(r[3]) : "r"(addr));
}
__device__ __forceinline__ void mma_bf16(float* d, const uint32_t* a, const uint32_t* b) {
    asm volatile("mma.sync.aligned.m16n8k16.row.col.f32.bf16.bf16.f32 "
                 "{%0,%1,%2,%3}, {%4,%5,%6,%7}, {%8,%9}, {%0,%1,%2,%3};"
                 : "+f"(d[0]), "+f"(d[1]), "+f"(d[2]), "+f"(d[3])
                 : "r"(a[0]), "r"(a[1]), "r"(a[2]), "r"(a[3]), "r"(b[0]), "r"(b[1]));
}
#define CP16(dst, src) \
    asm volatile("cp.async.ca.shared.global [%0], [%1], 16;" :: "r"(dst), "l"(src))
#define CP_COMMIT() asm volatile("cp.async.commit_group;")
#define CP_WAIT1()  asm volatile("cp.async.wait_group 1;")
#define CP_WAIT0()  asm volatile("cp.async.wait_group 0;")

// ---------------- kernel 1: merged prep — build ELL (blocks 0..124) | conv weights ----
__global__ void prep_build_conv(const float* __restrict__ L, const float* __restrict__ lmax,
                                const float* __restrict__ fc1W, const float* __restrict__ lin1W) {
    if (blockIdx.x < 125) {
        const int warp = (blockIdx.x * blockDim.x + threadIdx.x) >> 5;
        const int lane = threadIdx.x & 31;
        if (warp >= NV) return;
        const int v = warp;
        const float inv = 2.0f / lmax[0];
        int cnt = 0;
        #pragma unroll 4
        for (int c = 0; c < (NV + 31) / 32; ++c) {
            const int u = c * 32 + lane;
            float val = 0.0f;
            if (u < NV) val = L[(size_t)v * NV + u] * inv - (u == v ? 1.0f : 0.0f);
            const bool nz = (val != 0.0f);
            const unsigned m = __ballot_sync(0xffffffffu, nz);
            if (nz) {
                const int idx = cnt + __popc(m & ((1u << lane) - 1u));
                if (idx < MAXW) g_ell[v * MAXW + idx] = make_int2(u, __float_as_int(val));
            }
            cnt += __popc(m);
        }
        if (lane == 0) g_ell_len[v] = cnt < MAXW ? cnt : MAXW;
    } else {
        const int i = (blockIdx.x - 125) * blockDim.x + threadIdx.x;
        if (i < HIDD * 625) {
            const int n = i / 625, k = i - n * 625;
            __nv_bfloat16 h, l;
            bf16_split(fc1W[i], h, l);
            g_fc1h[n * KPAD + k] = h;
            g_fc1l[n * KPAD + k] = l;
        }
        if (i < HIDD * HIDD) {
            __nv_bfloat16 h, l;
            bf16_split(lin1W[i], h, l);
            g_lin1h[i] = h;
            g_lin1l[i] = l;
        }
    }
}

// ---------------- kernel 1b: deterministic rank sort (smem staged) ----------------
__global__ void sort_nodes() {
    __shared__ int sl[NV];
    const int tid = threadIdx.x;
    if (tid < NV) sl[tid] = g_ell_len[tid];
    __syncthreads();
    if (tid < NV) {
        const int len = sl[tid];
        int pos = 0;
        for (int u = 0; u < NV; ++u) {
            const int lu = sl[u];
            pos += (lu < len) || (lu == len && u < tid);
        }
        g_perm[pos] = tid;
    }
}

// ---------------- kernel 1c: lane-major transpose, rotated-class order ----------------
// 8-pass class scan (no local arrays -> no spill). Deterministic.
__global__ void transpose_ell() {
    const int s = blockIdx.x * blockDim.x + threadIdx.x;
    if (s >= NSLOT) return;
    const int grp = s >> 5, lane = s & 31;
    const int r = lane & 7;
    int v = -1, len = 0;
    if (s < NV) { v = g_perm[s]; len = g_ell_len[v]; }
    int2* dst = g_ellT + grp * (MAXW * 32) + lane;
    int jo = 0;
    for (int cc = 0; cc < 8; ++cc) {
        for (int j = 0; j < len; ++j) {
            const int2 e = g_ell[v * MAXW + j];
            if ((((e.x & 7) - r) & 7) == cc) dst[(jo++) * 32] = e;
        }
    }
    for (; jo < MAXW; ++jo) dst[jo * 32] = make_int2(0, 0);
}

// ---------------- kernel 2: fused cheby + cl1 + relu + maxpool -> bf16 hi/lo ----------
__global__ __launch_bounds__(1024, 1)
void cheby_fused(const float* __restrict__ x,
                 const float* __restrict__ W,
                 const float* __restrict__ bias) {
    extern __shared__ float sT[];
    float* sLo = sT;
    float* sHi = sT + CHEBK * PLANE;
    float* sW  = sT + 2 * CHEBK * PLANE;
    const int b0  = blockIdx.x * BT;
    const int tid = threadIdx.x;

    if (tid < NF * CHEBK) sW[tid] = W[tid];
    if (tid < NF) sW[NF * CHEBK + tid] = bias[tid];

    #pragma unroll
    for (int i = tid; i < NV * BT; i += 1024) {
        const int bb = i / NV, v = i - bb * NV;
        const float val = x[(size_t)(b0 + bb) * NV + v];
        if (bb < HBT) sLo[v * HBT + bb] = val;
        else          sHi[v * HBT + (bb - HBT)] = val;
    }
    __syncthreads();

    const int slot = tid;
    const int grp  = tid >> 5, lane = tid & 31;
    int v = 0, len = 0;
    if (slot < NV) { v = g_perm[slot]; len = g_ell_len[v]; }
    const int lm = __reduce_max_sync(0xffffffffu, len);
    const int2* __restrict__ ep = g_ellT + grp * (MAXW * 32) + lane;

    #pragma unroll
    for (int k = 1; k < CHEBK; ++k) {
        const float* __restrict__ Lo1 = sLo + (k - 1) * PLANE;
        const float* __restrict__ Hi1 = sHi + (k - 1) * PLANE;
        float4 A0 = make_float4(0.f, 0.f, 0.f, 0.f);
        float4 A1 = make_float4(0.f, 0.f, 0.f, 0.f);
        #pragma unroll 2
        for (int j = 0; j < lm; ++j) {
            const int2 e = __ldg(&ep[j * 32]);
            const float w = __int_as_float(e.y);
            const float4 t0 = *reinterpret_cast<const float4*>(Lo1 + e.x * HBT);
            const float4 t1 = *reinterpret_cast<const float4*>(Hi1 + e.x * HBT);
            A0.x = fmaf(w, t0.x, A0.x); A0.y = fmaf(w, t0.y, A0.y);
            A0.z = fmaf(w, t0.z, A0.z); A0.w = fmaf(w, t0.w, A0.w);
            A1.x = fmaf(w, t1.x, A1.x); A1.y = fmaf(w, t1.y, A1.y);
            A1.z = fmaf(w, t1.z, A1.z); A1.w = fmaf(w, t1.w, A1.w);
        }
        if (slot < NV) {
            float4* toL = reinterpret_cast<float4*>(sLo + k * PLANE + v * HBT);
            float4* toH = reinterpret_cast<float4*>(sHi + k * PLANE + v * HBT);
            if (k == 1) {
                *toL = A0; *toH = A1;
            } else {
                const float4 ma = *reinterpret_cast<const float4*>(sLo + (k - 2) * PLANE + v * HBT);
                const float4 mb = *reinterpret_cast<const float4*>(sHi + (k - 2) * PLANE + v * HBT);
                *toL = make_float4(2.f * A0.x - ma.x, 2.f * A0.y - ma.y,
                                   2.f * A0.z - ma.z, 2.f * A0.w - ma.w);
                *toH = make_float4(2.f * A1.x - mb.x, 2.f * A1.y - mb.y,
                                   2.f * A1.z - mb.z, 2.f * A1.w - mb.w);
            }
        }
        __syncthreads();
    }

    if (tid < 125 * BT) {
        const int bb = tid & (BT - 1);
        const int g  = tid / BT;
        const float* base = (bb < HBT) ? sLo : sHi;
        const int bo = bb & (HBT - 1);
        float m[NF];
        #pragma unroll
        for (int f = 0; f < NF; ++f) m[f] = -3.4e38f;
        #pragma unroll
        for (int vi = 0; vi < 8; ++vi) {
            const int vv = g * 8 + vi;
            float t[CHEBK];
            #pragma unroll
            for (int k = 0; k < CHEBK; ++k) t[k] = base[k * PLANE + vv * HBT + bo];
            #pragma unroll
            for (int f = 0; f < NF; ++f) {
                float s = sW[NF * CHEBK + f];
                #pragma unroll
                for (int k = 0; k < CHEBK; ++k) s = fmaf(sW[f * CHEBK + k], t[k], s);
                m[f] = fmaxf(m[f], s);
            }
        }
        const size_t op = (size_t)(b0 + bb) * KPAD + g * NF;
        #pragma unroll
        for (int f = 0; f < NF; ++f) {
            __nv_bfloat16 h, l;
            bf16_split(fmaxf(m[f], 0.0f), h, l);
            g_poolh[op + f] = h;
            g_pooll[op + f] = l;
        }
    }
}

// ---------------- kernels 3/4: 3-stage cp.async mma.sync bf16-split GEMM --------------
// CTA tile 128x64, 8 warps (4x2), warp tile 32x32 (2x4 m16n8k16 frags), 3 passes.
// 3 stages x 30720 B + 2304 B epilogue coeffs.
#define STG   30720
#define O_AL  10240
#define O_BH  20480
#define O_BL  25600
#define O_EP  (3 * STG)
#define GSM_TOT (O_EP + 576 * 4)

template <int EPI>
__global__ __launch_bounds__(256, 2)
void gemm_mma(const __nv_bfloat16* __restrict__ Ah, const __nv_bfloat16* __restrict__ Al,
              int lda,
              const __nv_bfloat16* __restrict__ Bh, const __nv_bfloat16* __restrict__ Bl,
              int ldb, int ktiles,
              const float* __restrict__ bias,
              const float* __restrict__ bn_gamma, const float* __restrict__ bn_beta,
              const float* __restrict__ bn_mean,  const float* __restrict__ bn_var,
              float* __restrict__ Cf,
              __nv_bfloat16* __restrict__ Ch, __nv_bfloat16* __restrict__ Cl, int ldc) {
    extern __shared__ char sm[];
    const uint32_t sbase = smem_u32(sm);

    const int tid = threadIdx.x, wid = tid >> 5, lane = tid & 31;
    const int wm = wid >> 1, wn = wid & 1;
    const int m0 = blockIdx.y * 128, n0 = blockIdx.x * 64;

    float acc[2][4][4];
    #pragma unroll
    for (int a = 0; a < 2; ++a)
        #pragma unroll
        for (int b = 0; b < 4; ++b)
            #pragma unroll
            for (int c = 0; c < 4; ++c) acc[a][b][c] = 0.0f;

    const int aRowL = tid >> 2, aOffL = (tid & 3) * 16;
    auto load_tile = [&](int t, int stage) {
        const uint32_t sb = sbase + stage * STG;
        #pragma unroll
        for (int i = 0; i < 2; ++i) {
            const int row = aRowL + i * 64;
            const uint32_t dst = sb + row * 80 + aOffL;
            const size_t go = (size_t)(m0 + row) * lda + t * 32 + (aOffL >> 1);
            CP16(dst, Ah + go);
            CP16(dst + O_AL, Al + go);
        }
        {
            const int row = tid >> 2;
            const uint32_t dst = sb + O_BH + row * 80 + aOffL;
            const size_t go = (size_t)(n0 + row) * ldb + t * 32 + (aOffL >> 1);
            CP16(dst, Bh + go);
            CP16(dst + (O_BL - O_BH), Bl + go);
        }
        CP_COMMIT();
    };

    const int aRow = wm * 32 + (lane & 15);
    const int aCol = (lane >> 4) * 8;
    const int bRow = wn * 32 + ((lane >> 4) * 8) + (lane & 7);
    const int bCol = ((lane >> 3) & 1) * 8;

    // prologue: 2 tiles in flight
    load_tile(0, 0);
    if (ktiles > 1) load_tile(1, 1);

    for (int t = 0; t < ktiles; ++t) {
        if (t + 1 < ktiles) CP_WAIT1(); else CP_WAIT0();
        __syncthreads();                       // tile t resident for all warps

        const uint32_t sb = sbase + (t % 3) * STG;
        #pragma unroll
        for (int kk = 0; kk < 2; ++kk) {
            uint32_t ah[2][4], al[2][4], bh[2][4], bl[2][4];
            #pragma unroll
            for (int mt = 0; mt < 2; ++mt) {
                const uint32_t off = (uint32_t)((aRow + mt * 16) * 80 + (kk * 16 + aCol) * 2);
                ldm_x4(sb + off, ah[mt]);
                ldm_x4(sb + O_AL + off, al[mt]);
            }
            #pragma unroll
            for (int nt2 = 0; nt2 < 2; ++nt2) {
                const uint32_t off = (uint32_t)((bRow + nt2 * 16) * 80 + (kk * 16 + bCol) * 2);
                ldm_x4(sb + O_BH + off, bh[nt2]);
                ldm_x4(sb + O_BL + off, bl[nt2]);
            }
            #pragma unroll
            for (int mt = 0; mt < 2; ++mt)
                #pragma unroll
                for (int nt = 0; nt < 4; ++nt) {
                    const uint32_t* fh = &bh[nt >> 1][(nt & 1) * 2];
                    const uint32_t* fl = &bl[nt >> 1][(nt & 1) * 2];
                    mma_bf16(acc[mt][nt], ah[mt], fh);
                    mma_bf16(acc[mt][nt], al[mt], fh);
                    mma_bf16(acc[mt][nt], ah[mt], fl);
                }
        }
        // issue next-next tile; overwrites stage (t+2)%3 == (t-1)%3, whose readers
        // all passed the barrier at the top of this iteration.
        if (t + 2 < ktiles) load_tile(t + 2, (t + 2) % 3);
    }

    __syncthreads();
    float* sEp = reinterpret_cast<float*>(sm + O_EP);
    if (tid < 64) {
        const int col = n0 + tid;
        sEp[tid] = __ldg(bias + col);
        if (EPI == 0) {
            #pragma unroll
            for (int l = 0; l < 4; ++l) {
                const int idx = l * HIDD + col;
                const float s = __ldg(bn_gamma + idx) * rsqrtf(__ldg(bn_var + idx) + 1e-5f);
                sEp[64 + l * 64 + tid]  = s;
                sEp[320 + l * 64 + tid] = __ldg(bn_beta + idx) - __ldg(bn_mean + idx) * s;
            }
        }
    }
    __syncthreads();

    #pragma unroll
    for (int mt = 0; mt < 2; ++mt) {
        const int row0 = m0 + wm * 32 + mt * 16 + (lane >> 2);
        #pragma unroll
        for (int nt = 0; nt < 4; ++nt) {
            const int cl = wn * 32 + nt * 8 + (lane & 3) * 2;
            const int col = n0 + cl;
            const float* d = acc[mt][nt];
            #pragma unroll
            for (int rr = 0; rr < 2; ++rr) {
                const int row = row0 + rr * 8;
                if (EPI == 0) {
                    __nv_bfloat16 hh[2], ll[2];
                    #pragma unroll
                    for (int q = 0; q < 2; ++q) {
                        float y = d[rr * 2 + q] + sEp[cl + q];
                        float z = 0.0f;
                        #pragma unroll
                        for (int l = 0; l < 4; ++l) {
                            y = fmaxf(fmaf(y, sEp[64 + l * 64 + cl + q],
                                           sEp[320 + l * 64 + cl + q]), 0.0f);
                            z = fmaxf(z, y);
                        }
                        bf16_split(z, hh[q], ll[q]);
                    }
                    __nv_bfloat162 th; th.x = hh[0]; th.y = hh[1];
                    __nv_bfloat162 tl; tl.x = ll[0]; tl.y = ll[1];
                    *reinterpret_cast<__nv_bfloat162*>(&Ch[(size_t)row * ldc + col]) = th;
                    *reinterpret_cast<__nv_bfloat162*>(&Cl[(size_t)row * ldc + col]) = tl;
                } else {
                    float2 o;
                    o.x = fmaxf(d[rr * 2 + 0] + sEp[cl + 0], 0.0f);
                    o.y = fmaxf(d[rr * 2 + 1] + sEp[cl + 1], 0.0f);
                    *reinterpret_cast<float2*>(&Cf[(size_t)row * ldc + col]) = o;
                }
            }
        }
    }
}

// ---------------- kernel 5: lin2 + log_softmax ----------------
__global__ void lin2_lsm(const float* __restrict__ Z2, const float* __restrict__ W2,
                         const float* __restrict__ b2, float* __restrict__ out) {
    const int gw   = (blockIdx.x * blockDim.x + threadIdx.x) >> 5;
    const int lane = threadIdx.x & 31;
    if (gw >= BATCH) return;
    const float* zr = Z2 + (size_t)gw * HIDD;
    float z[8];
    #pragma unroll
    for (int j = 0; j < 8; ++j) z[j] = zr[lane + 32 * j];

    float logit[NOUT];
    #pragma unroll
    for (int o = 0; o < NOUT; ++o) {
        float p = 0.0f;
        #pragma unroll
        for (int j = 0; j < 8; ++j) p += z[j] * __ldg(W2 + o * HIDD + lane + 32 * j);
        #pragma unroll
        for (int off = 16; off; off >>= 1) p += __shfl_xor_sync(0xffffffffu, p, off);
        logit[o] = p + __ldg(b2 + o);
    }
    float m = logit[0];
    #pragma unroll
    for (int o = 1; o < NOUT; ++o) m = fmaxf(m, logit[o]);
    float s = 0.0f;
    #pragma unroll
    for (int o = 0; o < NOUT; ++o) s += expf(logit[o] - m);
    const float lse = m + logf(s);
    if (lane < NOUT) out[(size_t)gw * NOUT + lane] = logit[lane] - lse;
}

// ---------------- launcher ----------------
extern "C" void kernel_launch(void* const* d_in, const int* in_sizes, int n_in,
                              void* d_out, int out_size) {
    const float* x        = (const float*)d_in[0];
    const float* L        = (const float*)d_in[1];
    const float* lmax     = (const float*)d_in[2];
    const float* cl1W     = (const float*)d_in[3];
    const float* cl1b     = (const float*)d_in[4];
    const float* fc1W     = (const float*)d_in[5];
    const float* fc1b     = (const float*)d_in[6];
    const float* bn_gamma = (const float*)d_in[7];
    const float* bn_beta  = (const float*)d_in[8];
    const float* bn_mean  = (const float*)d_in[9];
    const float* bn_var   = (const float*)d_in[10];
    const float* lin1W    = (const float*)d_in[11];
    const float* lin1b    = (const float*)d_in[12];
    const float* lin2W    = (const float*)d_in[13];
    const float* lin2b    = (const float*)d_in[14];
    float* out = (float*)d_out;

    __nv_bfloat16 *pPh, *pPl, *pF1h, *pF1l, *pL1h, *pL1l, *pZ1h, *pZ1l;
    float* pZ2;
    cudaGetSymbolAddress((void**)&pPh,  g_poolh);
    cudaGetSymbolAddress((void**)&pPl,  g_pooll);
    cudaGetSymbolAddress((void**)&pF1h, g_fc1h);
    cudaGetSymbolAddress((void**)&pF1l, g_fc1l);
    cudaGetSymbolAddress((void**)&pL1h, g_lin1h);
    cudaGetSymbolAddress((void**)&pL1l, g_lin1l);
    cudaGetSymbolAddress((void**)&pZ1h, g_z1h);
    cudaGetSymbolAddress((void**)&pZ1l, g_z1l);
    cudaGetSymbolAddress((void**)&pZ2,  g_z2);

    // 1) prep: merged (ELL build | weight conversion), then sort + rotated transpose
    prep_build_conv<<<125 + (HIDD * 625 + 255) / 256, 256>>>(L, lmax, fc1W, lin1W);
    sort_nodes<<<1, 1024>>>();
    transpose_ell<<<NSLOT / 256, 256>>>();

    // 2) fused chebyshev + cl1 + relu + maxpool -> bf16 hi/lo pool
    const int smem = (2 * CHEBK * PLANE + 32) * (int)sizeof(float);  // 160128 B
    cudaFuncSetAttribute(cheby_fused, cudaFuncAttributeMaxDynamicSharedMemorySize, smem);
    cheby_fused<<<BATCH / BT, 1024, smem>>>(x, cl1W, cl1b);

    // 3) fc1 + BN x4 + relu + JK-max  (K=640 padded), 3-stage pipelined mma.sync
    cudaFuncSetAttribute(gemm_mma<0>, cudaFuncAttributeMaxDynamicSharedMemorySize, GSM_TOT);
    cudaFuncSetAttribute(gemm_mma<1>, cudaFuncAttributeMaxDynamicSharedMemorySize, GSM_TOT);
    dim3 grid(HIDD / 64, BATCH / 128);   // (4, 64) = 256 CTAs
    gemm_mma<0><<<grid, 256, GSM_TOT>>>(pPh, pPl, KPAD, pF1h, pF1l, KPAD, KPAD / 32,
                                        fc1b, bn_gamma, bn_beta, bn_mean, bn_var,
                                        nullptr, pZ1h, pZ1l, HIDD);

    // 4) lin1 + relu  (K=256)
    gemm_mma<1><<<grid, 256, GSM_TOT>>>(pZ1h, pZ1l, HIDD, pL1h, pL1l, HIDD, HIDD / 32,
                                        lin1b, nullptr, nullptr, nullptr, nullptr,
                                        pZ2, nullptr, nullptr, HIDD);

    // 5) lin2 + log_softmax
    lin2_lsm<<<BATCH / 8, 256>>>(pZ2, lin2W, lin2b, out);
}